// round 9
// baseline (speedup 1.0000x reference)
#include <cuda_runtime.h>
#include <cuda_fp16.h>
#include <cstdint>

// Problem constants
#define BATCH 32
#define NTOK  1024
#define FDIM  512
#define GRP   16
#define SEQ   64
#define DDIM  256
#define WIN   32
#define OCH   512
#define TOUT  993          // NTOK - WIN + 1
#define KTOT  (WIN * DDIM) // 8192
#define NEG_SLOPE 0.2f

// Scratch (device globals; no allocs allowed)
__device__ __half g_mid[BATCH * NTOK * DDIM];         // 16 MB, fp16 mid
__device__ __half g_cwT[OCH * KTOT];                  // 8 MB, conv_w transposed [O][K], fp16

__device__ __forceinline__ unsigned f2tf(float v) {
    unsigned r;
    asm("cvt.rna.tf32.f32 %0, %1;" : "=r"(r) : "f"(v));
    return r;
}

__device__ __forceinline__ void cp16(unsigned smem, const void* g, int sz) {
    asm volatile("cp.async.ca.shared.global [%0], [%1], 16, %2;\n"
                 :: "r"(smem), "l"(g), "r"(sz));
}

__device__ __forceinline__ void ldsm4(unsigned* r, unsigned addr) {
    asm volatile("ldmatrix.sync.aligned.m8n8.x4.shared.b16 {%0,%1,%2,%3}, [%4];"
                 : "=r"(r[0]), "=r"(r[1]), "=r"(r[2]), "=r"(r[3]) : "r"(addr));
}

__device__ __forceinline__ void mma_tf32(float* c, const unsigned* a, const unsigned* b) {
    asm volatile(
        "mma.sync.aligned.m16n8k8.row.col.f32.tf32.tf32.f32 "
        "{%0,%1,%2,%3}, {%4,%5,%6,%7}, {%8,%9}, {%0,%1,%2,%3};\n"
        : "+f"(c[0]), "+f"(c[1]), "+f"(c[2]), "+f"(c[3])
        : "r"(a[0]), "r"(a[1]), "r"(a[2]), "r"(a[3]), "r"(b[0]), "r"(b[1]));
}

__device__ __forceinline__ void mma_f16(float* c, const unsigned* a, const unsigned* b) {
    asm volatile(
        "mma.sync.aligned.m16n8k16.row.col.f32.f16.f16.f32 "
        "{%0,%1,%2,%3}, {%4,%5,%6,%7}, {%8,%9}, {%0,%1,%2,%3};\n"
        : "+f"(c[0]), "+f"(c[1]), "+f"(c[2]), "+f"(c[3])
        : "r"(a[0]), "r"(a[1]), "r"(a[2]), "r"(a[3]), "r"(b[0]), "r"(b[1]));
}

// ===========================================================================
// Pre-pass: transpose conv_w [K=8192][O=512] -> g_cwT [O=512][K=8192], fp16
// ===========================================================================
__global__ __launch_bounds__(256)
void trans_cw_kernel(const float* __restrict__ cw) {
    __shared__ float tile[32][33];
    const int o0 = blockIdx.x * 32;
    const int k0 = blockIdx.y * 32;
    const int tx = threadIdx.x & 31;
    const int ty = threadIdx.x >> 5;
#pragma unroll
    for (int j = 0; j < 4; j++) {
        int k = ty + j * 8;
        tile[k][tx] = cw[(long)(k0 + k) * OCH + o0 + tx];
    }
    __syncthreads();
#pragma unroll
    for (int j = 0; j < 4; j++) {
        int o = ty + j * 8;
        g_cwT[(long)(o0 + o) * KTOT + k0 + tx] = __float2half_rn(tile[tx][o]);
    }
}

// ===========================================================================
// Kernel 1: gather + grouped GEMM via mma.sync tf32 (m16n8k8)
// CTA 128x128x16, 8 warps (4m x 2n), warp 32x64. M=2048, K=512, N=256.
// W read directly; tf32 rounding on both fragment sets. Writes fp16 mid.
// ===========================================================================
#define BK 16
#define AST 20
#define BST 136

__global__ __launch_bounds__(256, 2)
void gemm1_mma_kernel(const float* __restrict__ x, const int* __restrict__ idx,
                      const float* __restrict__ W, const float* __restrict__ bias) {
    const int grp = blockIdx.z;
    const int m0  = blockIdx.y * 128;
    const int n0  = blockIdx.x * 128;
    const int tid  = threadIdx.x;
    const int lane = tid & 31;
    const int warp = tid >> 5;
    const int wm = warp >> 1;
    const int wn = warp & 1;
    const int gi = lane >> 2;
    const int tl = lane & 3;

    __shared__ float As[2][128][AST];
    __shared__ float Bs[2][BK][BST];
    __shared__ int   rowbase[128];

    if (tid < 128) {
        int m  = m0 + tid;
        int bb = m >> 6;
        int s  = m & 63;
        rowbase[tid] = bb * NTOK + idx[grp * SEQ + s];
    }
    __syncthreads();

    const int am0 = tid >> 2;
    const int ak0 = (tid & 3) * 4;
    const int bn0 = (tid & 31) * 4;
    const int bk0 = tid >> 5;

    const long arow0 = (long)rowbase[am0] * FDIM;
    const long arow1 = (long)rowbase[am0 + 64] * FDIM;
    const float* Bsrc = W + (long)grp * FDIM * DDIM;

    unsigned as_base = (unsigned)__cvta_generic_to_shared(&As[0][0][0]);
    unsigned bs_base = (unsigned)__cvta_generic_to_shared(&Bs[0][0][0]);
    const unsigned as_stage = 128 * AST * 4;
    const unsigned bs_stage = BK * BST * 4;

    float acc[2][8][4];
#pragma unroll
    for (int mt = 0; mt < 2; mt++)
#pragma unroll
        for (int nt = 0; nt < 8; nt++)
#pragma unroll
            for (int i = 0; i < 4; i++) acc[mt][nt][i] = 0.f;

    const int NSTAGE = FDIM / BK;   // 32

    {
        cp16(as_base + (am0 * AST + ak0) * 4, x + arow0 + ak0, 16);
        cp16(as_base + ((am0 + 64) * AST + ak0) * 4, x + arow1 + ak0, 16);
#pragma unroll
        for (int it = 0; it < 2; it++) {
            int k = bk0 + it * 8;
            cp16(bs_base + (k * BST + bn0) * 4, Bsrc + (long)k * DDIM + n0 + bn0, 16);
        }
        asm volatile("cp.async.commit_group;\n");
    }

#pragma unroll 1
    for (int s = 0; s < NSTAGE; s++) {
        asm volatile("cp.async.wait_group 0;\n");
        __syncthreads();

        if (s + 1 < NSTAGE) {
            const int ks = (s + 1) * BK;
            const unsigned ab  = as_base + ((s + 1) & 1) * as_stage;
            const unsigned bb2 = bs_base + ((s + 1) & 1) * bs_stage;
            cp16(ab + (am0 * AST + ak0) * 4, x + arow0 + ks + ak0, 16);
            cp16(ab + ((am0 + 64) * AST + ak0) * 4, x + arow1 + ks + ak0, 16);
#pragma unroll
            for (int it = 0; it < 2; it++) {
                int k = bk0 + it * 8;
                cp16(bb2 + (k * BST + bn0) * 4, Bsrc + (long)(ks + k) * DDIM + n0 + bn0, 16);
            }
            asm volatile("cp.async.commit_group;\n");
        }

        const int cur = s & 1;
#pragma unroll
        for (int kk = 0; kk < BK; kk += 8) {
            unsigned af[2][4];
#pragma unroll
            for (int mt = 0; mt < 2; mt++) {
                int rm = wm * 32 + mt * 16;
                af[mt][0] = f2tf(As[cur][rm + gi     ][kk + tl    ]);
                af[mt][1] = f2tf(As[cur][rm + gi + 8 ][kk + tl    ]);
                af[mt][2] = f2tf(As[cur][rm + gi     ][kk + tl + 4]);
                af[mt][3] = f2tf(As[cur][rm + gi + 8 ][kk + tl + 4]);
            }
            unsigned bf[8][2];
#pragma unroll
            for (int nt = 0; nt < 8; nt++) {
                int cn = wn * 64 + nt * 8;
                bf[nt][0] = f2tf(Bs[cur][kk + tl    ][cn + gi]);
                bf[nt][1] = f2tf(Bs[cur][kk + tl + 4][cn + gi]);
            }
#pragma unroll
            for (int mt = 0; mt < 2; mt++)
#pragma unroll
                for (int nt = 0; nt < 8; nt++)
                    mma_tf32(acc[mt][nt], af[mt], bf[nt]);
        }
        __syncthreads();
    }

    // epilogue: + bias, round to fp16, scatter to g_mid[b, grp*64+s, d]
#pragma unroll
    for (int mt = 0; mt < 2; mt++) {
        int r0 = m0 + wm * 32 + mt * 16 + gi;
        int r1 = r0 + 8;
#pragma unroll
        for (int nt = 0; nt < 8; nt++) {
            int c = n0 + wn * 64 + nt * 8 + 2 * tl;
            float2 bv = *(const float2*)(bias + grp * DDIM + c);
            {
                int bb = r0 >> 6, s = r0 & 63;
                __half2* dst = (__half2*)(g_mid + ((long)(bb * NTOK + grp * SEQ + s)) * DDIM + c);
                *dst = __floats2half2_rn(acc[mt][nt][0] + bv.x, acc[mt][nt][1] + bv.y);
            }
            {
                int bb = r1 >> 6, s = r1 & 63;
                __half2* dst = (__half2*)(g_mid + ((long)(bb * NTOK + grp * SEQ + s)) * DDIM + c);
                *dst = __floats2half2_rn(acc[mt][nt][2] + bv.x, acc[mt][nt][3] + bv.y);
            }
        }
    }
}

// ===========================================================================
// Kernel 2: conv1d implicit GEMM, fp16 m16n8k16.
//   CTA 256x256, 16 warps (4m x 4n), warp 64x64, BKH=64 halves,
//   3-stage cp.async = 192 KB smem, 1 CTA/SM.
//   Rows 128B; 16B chunks XOR-swizzled: chunk' = chunk ^ (row & 7).
//   Fragment double-buffering across the 4 k16 slices per stage.
// ===========================================================================
#define BKH 64                       // k-halves per stage
#define TILE_B 32768                 // 256 * 64 * 2 bytes
#define SM_A 0
#define SM_B (3 * TILE_B)
#define SM_TOTAL_CONV (6 * TILE_B)   // 192 KB

__global__ __launch_bounds__(512, 1)
void conv_mma_kernel(const float* __restrict__ cb, float* __restrict__ y) {
    extern __shared__ __align__(128) char smem[];
    unsigned smem_base;
    asm("{ .reg .u64 t; cvta.to.shared.u64 t, %1; cvt.u32.u64 %0, t; }"
        : "=r"(smem_base) : "l"(smem));

    const int b  = blockIdx.z;
    const int t0 = blockIdx.y * 256;
    const int n0 = blockIdx.x * 256;
    const int tid  = threadIdx.x;
    const int lane = tid & 31;
    const int warp = tid >> 5;
    const int wm = warp >> 2;        // 0..3 -> m offset wm*64
    const int wn = warp & 3;         // 0..3 -> n offset wn*64
    const int gi = lane >> 2;
    const int tl = lane & 3;
    const int grp8 = lane >> 3;      // 0..3
    const int r8   = lane & 7;

    const __half* midb = g_mid + (long)b * NTOK * DDIM;

    float acc[4][8][4];
#pragma unroll
    for (int mt = 0; mt < 4; mt++)
#pragma unroll
        for (int nt = 0; nt < 8; nt++)
#pragma unroll
            for (int i = 0; i < 4; i++) acc[mt][nt][i] = 0.f;

    const int NS = KTOT / BKH;   // 128

    auto load_stage = [&](int it) {
        const int ks = it * BKH;         // k offset in halves
        const int w  = ks >> 8;          // window position (256 halves per w)
        const int d0 = ks & 255;         // d offset in halves
        const int buf = it % 3;
        const unsigned abase = smem_base + SM_A + buf * TILE_B;
        const unsigned bbase = smem_base + SM_B + buf * TILE_B;
#pragma unroll
        for (int i = 0; i < 4; i++) {
            int c   = tid + i * 512;     // 0..2047
            int row = c >> 3;            // 0..255
            int ch  = c & 7;             // 16B chunk = 8 halves
            int t   = t0 + row + w;
            cp16(abase + row * 128 + ((ch ^ (row & 7)) * 16),
                 midb + (long)t * DDIM + d0 + ch * 8, (t < NTOK) ? 16 : 0);
        }
#pragma unroll
        for (int i = 0; i < 4; i++) {
            int c   = tid + i * 512;
            int row = c >> 3;
            int ch  = c & 7;
            cp16(bbase + row * 128 + ((ch ^ (row & 7)) * 16),
                 g_cwT + (long)(n0 + row) * KTOT + ks + ch * 8, 16);
        }
        asm volatile("cp.async.commit_group;\n");
    };

    // fragment loader for one k16 slice (kc = slice*2 chunks)
    auto ldfrag = [&](unsigned af[4][4], unsigned bf[4][4],
                      int kc, unsigned abase, unsigned bbase) {
#pragma unroll
        for (int mt = 0; mt < 4; mt++) {
            int row = wm * 64 + mt * 16 + (grp8 & 1) * 8 + r8;
            int ch  = kc + (grp8 >> 1);
            ldsm4(af[mt], abase + row * 128 + ((ch ^ (row & 7)) * 16));
        }
#pragma unroll
        for (int q = 0; q < 4; q++) {
            int row = wn * 64 + q * 16 + (grp8 >> 1) * 8 + r8;
            int ch  = kc + (grp8 & 1);
            ldsm4(bf[q], bbase + row * 128 + ((ch ^ (row & 7)) * 16));
        }
    };

    load_stage(0);
    load_stage(1);

    unsigned af[2][4][4];
    unsigned bf[2][4][4];

#pragma unroll 1
    for (int s = 0; s < NS; s++) {
        if (s + 1 < NS) asm volatile("cp.async.wait_group 1;\n");
        else            asm volatile("cp.async.wait_group 0;\n");
        __syncthreads();

        if (s + 2 < NS) load_stage(s + 2);

        const int buf = s % 3;
        const unsigned abase = smem_base + SM_A + buf * TILE_B;
        const unsigned bbase = smem_base + SM_B + buf * TILE_B;

        ldfrag(af[0], bf[0], 0, abase, bbase);

#pragma unroll
        for (int k4 = 0; k4 < 4; k4++) {          // 4 k16 slices per stage
            const int cur = k4 & 1;
            if (k4 < 3)
                ldfrag(af[cur ^ 1], bf[cur ^ 1], (k4 + 1) * 2, abase, bbase);
#pragma unroll
            for (int mt = 0; mt < 4; mt++)
#pragma unroll
                for (int nt = 0; nt < 8; nt++)
                    mma_f16(acc[mt][nt], af[cur][mt], &bf[cur][nt >> 1][(nt & 1) * 2]);
        }
        // single sync per stage (3-buffer ring protected by next top sync)
    }

    // epilogue: bias + leaky relu
#pragma unroll
    for (int mt = 0; mt < 4; mt++) {
        int r0 = t0 + wm * 64 + mt * 16 + gi;
        int r1 = r0 + 8;
#pragma unroll
        for (int nt = 0; nt < 8; nt++) {
            int c = n0 + wn * 64 + nt * 8 + 2 * tl;
            float2 bv = *(const float2*)(cb + c);
            if (r0 < TOUT) {
                float v0 = acc[mt][nt][0] + bv.x;
                float v1 = acc[mt][nt][1] + bv.y;
                v0 = (v0 >= 0.f) ? v0 : NEG_SLOPE * v0;
                v1 = (v1 >= 0.f) ? v1 : NEG_SLOPE * v1;
                *(float2*)(y + ((long)b * TOUT + r0) * OCH + c) = make_float2(v0, v1);
            }
            if (r1 < TOUT) {
                float v2 = acc[mt][nt][2] + bv.x;
                float v3 = acc[mt][nt][3] + bv.y;
                v2 = (v2 >= 0.f) ? v2 : NEG_SLOPE * v2;
                v3 = (v3 >= 0.f) ? v3 : NEG_SLOPE * v3;
                *(float2*)(y + ((long)b * TOUT + r1) * OCH + c) = make_float2(v2, v3);
            }
        }
    }
}

// ===========================================================================
extern "C" void kernel_launch(void* const* d_in, const int* in_sizes, int n_in,
                              void* d_out, int out_size) {
    const float* x    = (const float*)d_in[0];
    const int*   idx  = (const int*)  d_in[1];
    const float* W    = (const float*)d_in[2];
    const float* bias = (const float*)d_in[3];
    const float* cw   = (const float*)d_in[4];
    const float* cb   = (const float*)d_in[5];
    float* y = (float*)d_out;

    cudaFuncSetAttribute(conv_mma_kernel,
                         cudaFuncAttributeMaxDynamicSharedMemorySize, SM_TOTAL_CONV);

    trans_cw_kernel<<<dim3(OCH / 32, KTOT / 32), 256>>>(cw);

    dim3 grid1(DDIM / 128, (BATCH * SEQ) / 128, GRP);   // (2, 16, 16)
    gemm1_mma_kernel<<<grid1, 256>>>(x, idx, W, bias);

    dim3 grid2(OCH / 256, NTOK / 256, BATCH);           // (2, 4, 32) = 256 CTAs
    conv_mma_kernel<<<grid2, 512, SM_TOTAL_CONV>>>(cb, y);
}

// round 10
// speedup vs baseline: 2.8080x; 2.8080x over previous
#include <cuda_runtime.h>
#include <cuda_fp16.h>
#include <cstdint>

// Problem constants
#define BATCH 32
#define NTOK  1024
#define FDIM  512
#define GRP   16
#define SEQ   64
#define DDIM  256
#define WIN   32
#define OCH   512
#define TOUT  993          // NTOK - WIN + 1
#define KTOT  (WIN * DDIM) // 8192
#define NEG_SLOPE 0.2f

// Scratch (device globals; no allocs allowed)
__device__ __half g_mid[BATCH * NTOK * DDIM];         // 16 MB, fp16 mid
__device__ __half g_cwT[OCH * KTOT];                  // 8 MB, conv_w transposed [O][K], fp16

__device__ __forceinline__ unsigned f2tf(float v) {
    unsigned r;
    asm("cvt.rna.tf32.f32 %0, %1;" : "=r"(r) : "f"(v));
    return r;
}

__device__ __forceinline__ void cp16(unsigned smem, const void* g, int sz) {
    asm volatile("cp.async.ca.shared.global [%0], [%1], 16, %2;\n"
                 :: "r"(smem), "l"(g), "r"(sz));
}

__device__ __forceinline__ void ldsm4(unsigned* r, unsigned addr) {
    asm volatile("ldmatrix.sync.aligned.m8n8.x4.shared.b16 {%0,%1,%2,%3}, [%4];"
                 : "=r"(r[0]), "=r"(r[1]), "=r"(r[2]), "=r"(r[3]) : "r"(addr));
}

__device__ __forceinline__ void mma_tf32(float* c, const unsigned* a, const unsigned* b) {
    asm volatile(
        "mma.sync.aligned.m16n8k8.row.col.f32.tf32.tf32.f32 "
        "{%0,%1,%2,%3}, {%4,%5,%6,%7}, {%8,%9}, {%0,%1,%2,%3};\n"
        : "+f"(c[0]), "+f"(c[1]), "+f"(c[2]), "+f"(c[3])
        : "r"(a[0]), "r"(a[1]), "r"(a[2]), "r"(a[3]), "r"(b[0]), "r"(b[1]));
}

__device__ __forceinline__ void mma_f16(float* c, const unsigned* a, const unsigned* b) {
    asm volatile(
        "mma.sync.aligned.m16n8k16.row.col.f32.f16.f16.f32 "
        "{%0,%1,%2,%3}, {%4,%5,%6,%7}, {%8,%9}, {%0,%1,%2,%3};\n"
        : "+f"(c[0]), "+f"(c[1]), "+f"(c[2]), "+f"(c[3])
        : "r"(a[0]), "r"(a[1]), "r"(a[2]), "r"(a[3]), "r"(b[0]), "r"(b[1]));
}

// ===========================================================================
// Pre-pass: transpose conv_w [K=8192][O=512] -> g_cwT [O=512][K=8192], fp16
// ===========================================================================
__global__ __launch_bounds__(256)
void trans_cw_kernel(const float* __restrict__ cw) {
    __shared__ float tile[32][33];
    const int o0 = blockIdx.x * 32;
    const int k0 = blockIdx.y * 32;
    const int tx = threadIdx.x & 31;
    const int ty = threadIdx.x >> 5;
#pragma unroll
    for (int j = 0; j < 4; j++) {
        int k = ty + j * 8;
        tile[k][tx] = cw[(long)(k0 + k) * OCH + o0 + tx];
    }
    __syncthreads();
#pragma unroll
    for (int j = 0; j < 4; j++) {
        int o = ty + j * 8;
        g_cwT[(long)(o0 + o) * KTOT + k0 + tx] = __float2half_rn(tile[tx][o]);
    }
}

// ===========================================================================
// Kernel 1: gather + grouped GEMM via mma.sync tf32 (m16n8k8)
// CTA 128x128x16, 8 warps (4m x 2n), warp 32x64. M=2048, K=512, N=256.
// W read directly; tf32 rounding on both fragment sets. Writes fp16 mid.
// ===========================================================================
#define BK 16
#define AST 20
#define BST 136

__global__ __launch_bounds__(256, 2)
void gemm1_mma_kernel(const float* __restrict__ x, const int* __restrict__ idx,
                      const float* __restrict__ W, const float* __restrict__ bias) {
    const int grp = blockIdx.z;
    const int m0  = blockIdx.y * 128;
    const int n0  = blockIdx.x * 128;
    const int tid  = threadIdx.x;
    const int lane = tid & 31;
    const int warp = tid >> 5;
    const int wm = warp >> 1;
    const int wn = warp & 1;
    const int gi = lane >> 2;
    const int tl = lane & 3;

    __shared__ float As[2][128][AST];
    __shared__ float Bs[2][BK][BST];
    __shared__ int   rowbase[128];

    if (tid < 128) {
        int m  = m0 + tid;
        int bb = m >> 6;
        int s  = m & 63;
        rowbase[tid] = bb * NTOK + idx[grp * SEQ + s];
    }
    __syncthreads();

    const int am0 = tid >> 2;
    const int ak0 = (tid & 3) * 4;
    const int bn0 = (tid & 31) * 4;
    const int bk0 = tid >> 5;

    const long arow0 = (long)rowbase[am0] * FDIM;
    const long arow1 = (long)rowbase[am0 + 64] * FDIM;
    const float* Bsrc = W + (long)grp * FDIM * DDIM;

    unsigned as_base = (unsigned)__cvta_generic_to_shared(&As[0][0][0]);
    unsigned bs_base = (unsigned)__cvta_generic_to_shared(&Bs[0][0][0]);
    const unsigned as_stage = 128 * AST * 4;
    const unsigned bs_stage = BK * BST * 4;

    float acc[2][8][4];
#pragma unroll
    for (int mt = 0; mt < 2; mt++)
#pragma unroll
        for (int nt = 0; nt < 8; nt++)
#pragma unroll
            for (int i = 0; i < 4; i++) acc[mt][nt][i] = 0.f;

    const int NSTAGE = FDIM / BK;   // 32

    {
        cp16(as_base + (am0 * AST + ak0) * 4, x + arow0 + ak0, 16);
        cp16(as_base + ((am0 + 64) * AST + ak0) * 4, x + arow1 + ak0, 16);
#pragma unroll
        for (int it = 0; it < 2; it++) {
            int k = bk0 + it * 8;
            cp16(bs_base + (k * BST + bn0) * 4, Bsrc + (long)k * DDIM + n0 + bn0, 16);
        }
        asm volatile("cp.async.commit_group;\n");
    }

#pragma unroll 1
    for (int s = 0; s < NSTAGE; s++) {
        asm volatile("cp.async.wait_group 0;\n");
        __syncthreads();

        if (s + 1 < NSTAGE) {
            const int ks = (s + 1) * BK;
            const unsigned ab  = as_base + ((s + 1) & 1) * as_stage;
            const unsigned bb2 = bs_base + ((s + 1) & 1) * bs_stage;
            cp16(ab + (am0 * AST + ak0) * 4, x + arow0 + ks + ak0, 16);
            cp16(ab + ((am0 + 64) * AST + ak0) * 4, x + arow1 + ks + ak0, 16);
#pragma unroll
            for (int it = 0; it < 2; it++) {
                int k = bk0 + it * 8;
                cp16(bb2 + (k * BST + bn0) * 4, Bsrc + (long)(ks + k) * DDIM + n0 + bn0, 16);
            }
            asm volatile("cp.async.commit_group;\n");
        }

        const int cur = s & 1;
#pragma unroll
        for (int kk = 0; kk < BK; kk += 8) {
            unsigned af[2][4];
#pragma unroll
            for (int mt = 0; mt < 2; mt++) {
                int rm = wm * 32 + mt * 16;
                af[mt][0] = f2tf(As[cur][rm + gi     ][kk + tl    ]);
                af[mt][1] = f2tf(As[cur][rm + gi + 8 ][kk + tl    ]);
                af[mt][2] = f2tf(As[cur][rm + gi     ][kk + tl + 4]);
                af[mt][3] = f2tf(As[cur][rm + gi + 8 ][kk + tl + 4]);
            }
            unsigned bf[8][2];
#pragma unroll
            for (int nt = 0; nt < 8; nt++) {
                int cn = wn * 64 + nt * 8;
                bf[nt][0] = f2tf(Bs[cur][kk + tl    ][cn + gi]);
                bf[nt][1] = f2tf(Bs[cur][kk + tl + 4][cn + gi]);
            }
#pragma unroll
            for (int mt = 0; mt < 2; mt++)
#pragma unroll
                for (int nt = 0; nt < 8; nt++)
                    mma_tf32(acc[mt][nt], af[mt], bf[nt]);
        }
        __syncthreads();
    }

    // epilogue: + bias, round to fp16, scatter to g_mid[b, grp*64+s, d]
#pragma unroll
    for (int mt = 0; mt < 2; mt++) {
        int r0 = m0 + wm * 32 + mt * 16 + gi;
        int r1 = r0 + 8;
#pragma unroll
        for (int nt = 0; nt < 8; nt++) {
            int c = n0 + wn * 64 + nt * 8 + 2 * tl;
            float2 bv = *(const float2*)(bias + grp * DDIM + c);
            {
                int bb = r0 >> 6, s = r0 & 63;
                __half2* dst = (__half2*)(g_mid + ((long)(bb * NTOK + grp * SEQ + s)) * DDIM + c);
                *dst = __floats2half2_rn(acc[mt][nt][0] + bv.x, acc[mt][nt][1] + bv.y);
            }
            {
                int bb = r1 >> 6, s = r1 & 63;
                __half2* dst = (__half2*)(g_mid + ((long)(bb * NTOK + grp * SEQ + s)) * DDIM + c);
                *dst = __floats2half2_rn(acc[mt][nt][2] + bv.x, acc[mt][nt][3] + bv.y);
            }
        }
    }
}

// ===========================================================================
// Kernel 2: conv1d implicit GEMM, fp16 m16n8k16.
//   CTA 128x256, 8 warps (2m x 4n), warp 64x64, 256 threads (FULL 255-reg
//   budget per thread — no spills), BKH=64, 3-stage cp.async = 144 KB smem,
//   1 CTA/SM. Rows 128B; 16B chunks XOR-swizzled: chunk' = chunk ^ (row & 7).
//   Fragment double-buffering across the 4 k16 slices per stage.
// ===========================================================================
#define BKH 64                       // k-halves per stage
#define A_TILE 16384                 // 128 * 64 * 2 bytes
#define B_TILE 32768                 // 256 * 64 * 2 bytes
#define STAGE_B (A_TILE + B_TILE)    // 48 KB
#define SM_TOTAL_CONV (3 * STAGE_B)  // 144 KB

__global__ __launch_bounds__(256, 1)
void conv_mma_kernel(const float* __restrict__ cb, float* __restrict__ y) {
    extern __shared__ __align__(128) char smem[];
    unsigned smem_base;
    asm("{ .reg .u64 t; cvta.to.shared.u64 t, %1; cvt.u32.u64 %0, t; }"
        : "=r"(smem_base) : "l"(smem));

    const int b  = blockIdx.z;
    const int t0 = blockIdx.y * 128;
    const int n0 = blockIdx.x * 256;
    const int tid  = threadIdx.x;
    const int lane = tid & 31;
    const int warp = tid >> 5;
    const int wm = warp >> 2;        // 0..1 -> m offset wm*64
    const int wn = warp & 3;         // 0..3 -> n offset wn*64
    const int gi = lane >> 2;
    const int tl = lane & 3;
    const int grp8 = lane >> 3;      // 0..3
    const int r8   = lane & 7;

    const __half* midb = g_mid + (long)b * NTOK * DDIM;

    float acc[4][8][4];
#pragma unroll
    for (int mt = 0; mt < 4; mt++)
#pragma unroll
        for (int nt = 0; nt < 8; nt++)
#pragma unroll
            for (int i = 0; i < 4; i++) acc[mt][nt][i] = 0.f;

    const int NS = KTOT / BKH;   // 128

    auto load_stage = [&](int it) {
        const int ks = it * BKH;         // k offset in halves
        const int w  = ks >> 8;          // window position (256 halves per w)
        const int d0 = ks & 255;         // d offset in halves
        const int buf = it % 3;
        const unsigned abase = smem_base + buf * STAGE_B;
        const unsigned bbase = abase + A_TILE;
        // A: 128 rows x 8 chunks = 1024 -> 4 per thread
#pragma unroll
        for (int i = 0; i < 4; i++) {
            int c   = tid + i * 256;     // 0..1023
            int row = c >> 3;            // 0..127
            int ch  = c & 7;             // 16B chunk = 8 halves
            int t   = t0 + row + w;
            cp16(abase + row * 128 + ((ch ^ (row & 7)) * 16),
                 midb + (long)t * DDIM + d0 + ch * 8, (t < NTOK) ? 16 : 0);
        }
        // B: 256 rows x 8 chunks = 2048 -> 8 per thread
#pragma unroll
        for (int i = 0; i < 8; i++) {
            int c   = tid + i * 256;
            int row = c >> 3;            // 0..255
            int ch  = c & 7;
            cp16(bbase + row * 128 + ((ch ^ (row & 7)) * 16),
                 g_cwT + (long)(n0 + row) * KTOT + ks + ch * 8, 16);
        }
        asm volatile("cp.async.commit_group;\n");
    };

    // fragment loader for one k16 slice (kc = slice*2 chunks)
    auto ldfrag = [&](unsigned af[4][4], unsigned bf[4][4],
                      int kc, unsigned abase, unsigned bbase) {
#pragma unroll
        for (int mt = 0; mt < 4; mt++) {
            int row = wm * 64 + mt * 16 + (grp8 & 1) * 8 + r8;
            int ch  = kc + (grp8 >> 1);
            ldsm4(af[mt], abase + row * 128 + ((ch ^ (row & 7)) * 16));
        }
#pragma unroll
        for (int q = 0; q < 4; q++) {
            int row = wn * 64 + q * 16 + (grp8 >> 1) * 8 + r8;
            int ch  = kc + (grp8 & 1);
            ldsm4(bf[q], bbase + row * 128 + ((ch ^ (row & 7)) * 16));
        }
    };

    load_stage(0);
    load_stage(1);

    unsigned af[2][4][4];
    unsigned bf[2][4][4];

#pragma unroll 1
    for (int s = 0; s < NS; s++) {
        if (s + 1 < NS) asm volatile("cp.async.wait_group 1;\n");
        else            asm volatile("cp.async.wait_group 0;\n");
        __syncthreads();

        if (s + 2 < NS) load_stage(s + 2);

        const int buf = s % 3;
        const unsigned abase = smem_base + buf * STAGE_B;
        const unsigned bbase = abase + A_TILE;

        ldfrag(af[0], bf[0], 0, abase, bbase);

#pragma unroll
        for (int k4 = 0; k4 < 4; k4++) {          // 4 k16 slices per stage
            const int cur = k4 & 1;
            if (k4 < 3)
                ldfrag(af[cur ^ 1], bf[cur ^ 1], (k4 + 1) * 2, abase, bbase);
#pragma unroll
            for (int mt = 0; mt < 4; mt++)
#pragma unroll
                for (int nt = 0; nt < 8; nt++)
                    mma_f16(acc[mt][nt], af[cur][mt], &bf[cur][nt >> 1][(nt & 1) * 2]);
        }
        // single sync per stage (3-buffer ring protected by next top sync)
    }

    // epilogue: bias + leaky relu
#pragma unroll
    for (int mt = 0; mt < 4; mt++) {
        int r0 = t0 + wm * 64 + mt * 16 + gi;
        int r1 = r0 + 8;
#pragma unroll
        for (int nt = 0; nt < 8; nt++) {
            int c = n0 + wn * 64 + nt * 8 + 2 * tl;
            float2 bv = *(const float2*)(cb + c);
            if (r0 < TOUT) {
                float v0 = acc[mt][nt][0] + bv.x;
                float v1 = acc[mt][nt][1] + bv.y;
                v0 = (v0 >= 0.f) ? v0 : NEG_SLOPE * v0;
                v1 = (v1 >= 0.f) ? v1 : NEG_SLOPE * v1;
                *(float2*)(y + ((long)b * TOUT + r0) * OCH + c) = make_float2(v0, v1);
            }
            if (r1 < TOUT) {
                float v2 = acc[mt][nt][2] + bv.x;
                float v3 = acc[mt][nt][3] + bv.y;
                v2 = (v2 >= 0.f) ? v2 : NEG_SLOPE * v2;
                v3 = (v3 >= 0.f) ? v3 : NEG_SLOPE * v3;
                *(float2*)(y + ((long)b * TOUT + r1) * OCH + c) = make_float2(v2, v3);
            }
        }
    }
}

// ===========================================================================
extern "C" void kernel_launch(void* const* d_in, const int* in_sizes, int n_in,
                              void* d_out, int out_size) {
    const float* x    = (const float*)d_in[0];
    const int*   idx  = (const int*)  d_in[1];
    const float* W    = (const float*)d_in[2];
    const float* bias = (const float*)d_in[3];
    const float* cw   = (const float*)d_in[4];
    const float* cb   = (const float*)d_in[5];
    float* y = (float*)d_out;

    cudaFuncSetAttribute(conv_mma_kernel,
                         cudaFuncAttributeMaxDynamicSharedMemorySize, SM_TOTAL_CONV);

    trans_cw_kernel<<<dim3(OCH / 32, KTOT / 32), 256>>>(cw);

    dim3 grid1(DDIM / 128, (BATCH * SEQ) / 128, GRP);   // (2, 16, 16)
    gemm1_mma_kernel<<<grid1, 256>>>(x, idx, W, bias);

    dim3 grid2(OCH / 256, NTOK / 128, BATCH);           // (2, 8, 32) = 512 CTAs
    conv_mma_kernel<<<grid2, 256, SM_TOTAL_CONV>>>(cb, y);
}

// round 11
// speedup vs baseline: 3.0530x; 1.0872x over previous
#include <cuda_runtime.h>
#include <cuda_fp16.h>
#include <cstdint>

// Problem constants
#define BATCH 32
#define NTOK  1024
#define FDIM  512
#define GRP   16
#define SEQ   64
#define DDIM  256
#define WIN   32
#define OCH   512
#define TOUT  993          // NTOK - WIN + 1
#define KTOT  (WIN * DDIM) // 8192
#define NEG_SLOPE 0.2f

// Scratch (device globals; no allocs allowed)
__device__ __half g_mid[BATCH * NTOK * DDIM];         // 16 MB, fp16 mid
__device__ __half g_cwT[OCH * KTOT];                  // 8 MB, conv_w transposed [O][K], fp16

__device__ __forceinline__ unsigned f2tf(float v) {
    unsigned r;
    asm("cvt.rna.tf32.f32 %0, %1;" : "=r"(r) : "f"(v));
    return r;
}

__device__ __forceinline__ void cp16(unsigned smem, const void* g, int sz) {
    asm volatile("cp.async.ca.shared.global [%0], [%1], 16, %2;\n"
                 :: "r"(smem), "l"(g), "r"(sz));
}

__device__ __forceinline__ void ldsm4(unsigned* r, unsigned addr) {
    asm volatile("ldmatrix.sync.aligned.m8n8.x4.shared.b16 {%0,%1,%2,%3}, [%4];"
                 : "=r"(r[0]), "=r"(r[1]), "=r"(r[2]), "=r"(r[3]) : "r"(addr));
}

__device__ __forceinline__ void mma_tf32(float* c, const unsigned* a, const unsigned* b) {
    asm volatile(
        "mma.sync.aligned.m16n8k8.row.col.f32.tf32.tf32.f32 "
        "{%0,%1,%2,%3}, {%4,%5,%6,%7}, {%8,%9}, {%0,%1,%2,%3};\n"
        : "+f"(c[0]), "+f"(c[1]), "+f"(c[2]), "+f"(c[3])
        : "r"(a[0]), "r"(a[1]), "r"(a[2]), "r"(a[3]), "r"(b[0]), "r"(b[1]));
}

__device__ __forceinline__ void mma_f16(float* c, const unsigned* a, const unsigned* b) {
    asm volatile(
        "mma.sync.aligned.m16n8k16.row.col.f32.f16.f16.f32 "
        "{%0,%1,%2,%3}, {%4,%5,%6,%7}, {%8,%9}, {%0,%1,%2,%3};\n"
        : "+f"(c[0]), "+f"(c[1]), "+f"(c[2]), "+f"(c[3])
        : "r"(a[0]), "r"(a[1]), "r"(a[2]), "r"(a[3]), "r"(b[0]), "r"(b[1]));
}

__device__ __forceinline__ void mbar_wait(unsigned mbar, int parity) {
    asm volatile(
        "{\n\t"
        ".reg .pred P1;\n\t"
        "WL_%=:\n\t"
        "mbarrier.try_wait.parity.shared.b64 P1, [%0], %1, 0x989680;\n\t"
        "@P1 bra.uni WD_%=;\n\t"
        "bra.uni WL_%=;\n\t"
        "WD_%=:\n\t"
        "}"
        :: "r"(mbar), "r"(parity) : "memory");
}

// ===========================================================================
// Pre-pass: transpose conv_w [K=8192][O=512] -> g_cwT [O=512][K=8192], fp16
// ===========================================================================
__global__ __launch_bounds__(256)
void trans_cw_kernel(const float* __restrict__ cw) {
    __shared__ float tile[32][33];
    const int o0 = blockIdx.x * 32;
    const int k0 = blockIdx.y * 32;
    const int tx = threadIdx.x & 31;
    const int ty = threadIdx.x >> 5;
#pragma unroll
    for (int j = 0; j < 4; j++) {
        int k = ty + j * 8;
        tile[k][tx] = cw[(long)(k0 + k) * OCH + o0 + tx];
    }
    __syncthreads();
#pragma unroll
    for (int j = 0; j < 4; j++) {
        int o = ty + j * 8;
        g_cwT[(long)(o0 + o) * KTOT + k0 + tx] = __float2half_rn(tile[tx][o]);
    }
}

// ===========================================================================
// Kernel 1: gather + grouped GEMM via mma.sync tf32 (m16n8k8)
// CTA 128x128x16, 8 warps (4m x 2n), warp 32x64. M=2048, K=512, N=256.
// W read directly; tf32 rounding on both fragment sets. Writes fp16 mid.
// ===========================================================================
#define BK 16
#define AST 20
#define BST 136

__global__ __launch_bounds__(256, 2)
void gemm1_mma_kernel(const float* __restrict__ x, const int* __restrict__ idx,
                      const float* __restrict__ W, const float* __restrict__ bias) {
    const int grp = blockIdx.z;
    const int m0  = blockIdx.y * 128;
    const int n0  = blockIdx.x * 128;
    const int tid  = threadIdx.x;
    const int lane = tid & 31;
    const int warp = tid >> 5;
    const int wm = warp >> 1;
    const int wn = warp & 1;
    const int gi = lane >> 2;
    const int tl = lane & 3;

    __shared__ float As[2][128][AST];
    __shared__ float Bs[2][BK][BST];
    __shared__ int   rowbase[128];

    if (tid < 128) {
        int m  = m0 + tid;
        int bb = m >> 6;
        int s  = m & 63;
        rowbase[tid] = bb * NTOK + idx[grp * SEQ + s];
    }
    __syncthreads();

    const int am0 = tid >> 2;
    const int ak0 = (tid & 3) * 4;
    const int bn0 = (tid & 31) * 4;
    const int bk0 = tid >> 5;

    const long arow0 = (long)rowbase[am0] * FDIM;
    const long arow1 = (long)rowbase[am0 + 64] * FDIM;
    const float* Bsrc = W + (long)grp * FDIM * DDIM;

    unsigned as_base = (unsigned)__cvta_generic_to_shared(&As[0][0][0]);
    unsigned bs_base = (unsigned)__cvta_generic_to_shared(&Bs[0][0][0]);
    const unsigned as_stage = 128 * AST * 4;
    const unsigned bs_stage = BK * BST * 4;

    float acc[2][8][4];
#pragma unroll
    for (int mt = 0; mt < 2; mt++)
#pragma unroll
        for (int nt = 0; nt < 8; nt++)
#pragma unroll
            for (int i = 0; i < 4; i++) acc[mt][nt][i] = 0.f;

    const int NSTAGE = FDIM / BK;   // 32

    {
        cp16(as_base + (am0 * AST + ak0) * 4, x + arow0 + ak0, 16);
        cp16(as_base + ((am0 + 64) * AST + ak0) * 4, x + arow1 + ak0, 16);
#pragma unroll
        for (int it = 0; it < 2; it++) {
            int k = bk0 + it * 8;
            cp16(bs_base + (k * BST + bn0) * 4, Bsrc + (long)k * DDIM + n0 + bn0, 16);
        }
        asm volatile("cp.async.commit_group;\n");
    }

#pragma unroll 1
    for (int s = 0; s < NSTAGE; s++) {
        asm volatile("cp.async.wait_group 0;\n");
        __syncthreads();

        if (s + 1 < NSTAGE) {
            const int ks = (s + 1) * BK;
            const unsigned ab  = as_base + ((s + 1) & 1) * as_stage;
            const unsigned bb2 = bs_base + ((s + 1) & 1) * bs_stage;
            cp16(ab + (am0 * AST + ak0) * 4, x + arow0 + ks + ak0, 16);
            cp16(ab + ((am0 + 64) * AST + ak0) * 4, x + arow1 + ks + ak0, 16);
#pragma unroll
            for (int it = 0; it < 2; it++) {
                int k = bk0 + it * 8;
                cp16(bb2 + (k * BST + bn0) * 4, Bsrc + (long)(ks + k) * DDIM + n0 + bn0, 16);
            }
            asm volatile("cp.async.commit_group;\n");
        }

        const int cur = s & 1;
#pragma unroll
        for (int kk = 0; kk < BK; kk += 8) {
            unsigned af[2][4];
#pragma unroll
            for (int mt = 0; mt < 2; mt++) {
                int rm = wm * 32 + mt * 16;
                af[mt][0] = f2tf(As[cur][rm + gi     ][kk + tl    ]);
                af[mt][1] = f2tf(As[cur][rm + gi + 8 ][kk + tl    ]);
                af[mt][2] = f2tf(As[cur][rm + gi     ][kk + tl + 4]);
                af[mt][3] = f2tf(As[cur][rm + gi + 8 ][kk + tl + 4]);
            }
            unsigned bf[8][2];
#pragma unroll
            for (int nt = 0; nt < 8; nt++) {
                int cn = wn * 64 + nt * 8;
                bf[nt][0] = f2tf(Bs[cur][kk + tl    ][cn + gi]);
                bf[nt][1] = f2tf(Bs[cur][kk + tl + 4][cn + gi]);
            }
#pragma unroll
            for (int mt = 0; mt < 2; mt++)
#pragma unroll
                for (int nt = 0; nt < 8; nt++)
                    mma_tf32(acc[mt][nt], af[mt], bf[nt]);
        }
        __syncthreads();
    }

    // epilogue: + bias, round to fp16, scatter to g_mid[b, grp*64+s, d]
#pragma unroll
    for (int mt = 0; mt < 2; mt++) {
        int r0 = m0 + wm * 32 + mt * 16 + gi;
        int r1 = r0 + 8;
#pragma unroll
        for (int nt = 0; nt < 8; nt++) {
            int c = n0 + wn * 64 + nt * 8 + 2 * tl;
            float2 bv = *(const float2*)(bias + grp * DDIM + c);
            {
                int bb = r0 >> 6, s = r0 & 63;
                __half2* dst = (__half2*)(g_mid + ((long)(bb * NTOK + grp * SEQ + s)) * DDIM + c);
                *dst = __floats2half2_rn(acc[mt][nt][0] + bv.x, acc[mt][nt][1] + bv.y);
            }
            {
                int bb = r1 >> 6, s = r1 & 63;
                __half2* dst = (__half2*)(g_mid + ((long)(bb * NTOK + grp * SEQ + s)) * DDIM + c);
                *dst = __floats2half2_rn(acc[mt][nt][2] + bv.x, acc[mt][nt][3] + bv.y);
            }
        }
    }
}

// ===========================================================================
// Kernel 2: conv1d implicit GEMM, fp16 m16n8k16, WARP-SPECIALIZED.
//   CTA 128x128, 160 threads: warps 0-3 = consumers (64x64 tiles, 2m x 2n),
//   warp 4 = producer (all cp.async). 3 smem slots, mbarrier handoff:
//     full[slot]  (count 32): producer cp.async.mbarrier.arrive.noinc
//     empty[slot] (count 4):  one elected lane per consumer warp arrives
//   No __syncthreads in the main loop. 2 CTAs/SM.
//   Rows 128B; 16B chunks XOR-swizzled: chunk' = chunk ^ (row & 7).
// ===========================================================================
#define BKH 64                       // k-halves per stage
#define A_TILE 16384                 // 128 * 64 * 2 bytes
#define STAGE_B 32768                // A + B
#define NSLOT 3
#define SM_DATA 128                  // stage buffers start (mbar region below)
#define SM_TOTAL_CONV (SM_DATA + NSLOT * STAGE_B)   // 96 KB + 128

__global__ __launch_bounds__(160, 2)
void conv_mma_kernel(const float* __restrict__ cb, float* __restrict__ y) {
    extern __shared__ __align__(128) char smem[];
    unsigned smem_base;
    asm("{ .reg .u64 t; cvta.to.shared.u64 t, %1; cvt.u32.u64 %0, t; }"
        : "=r"(smem_base) : "l"(smem));

    const int b  = blockIdx.z;
    const int t0 = blockIdx.y * 128;
    const int n0 = blockIdx.x * 128;
    const int tid  = threadIdx.x;
    const int lane = tid & 31;
    const int warp = tid >> 5;

    const __half* midb = g_mid + (long)b * NTOK * DDIM;
    const int NS = KTOT / BKH;   // 128

    // mbarrier addresses
    const unsigned mb_full0  = smem_base + 0;   // +8*slot
    const unsigned mb_empty0 = smem_base + 24;  // +8*slot

    if (tid == 0) {
#pragma unroll
        for (int j = 0; j < NSLOT; j++) {
            asm volatile("mbarrier.init.shared.b64 [%0], 32;" :: "r"(mb_full0 + 8u * j) : "memory");
            asm volatile("mbarrier.init.shared.b64 [%0], 4;"  :: "r"(mb_empty0 + 8u * j) : "memory");
        }
    }
    __syncthreads();

    if (warp == 4) {
        // ----------------- PRODUCER -----------------
#pragma unroll 1
        for (int s = 0; s < NS; s++) {
            const int slot = s % NSLOT;
            if (s >= NSLOT) {
                int pu = ((s / NSLOT) - 1) & 1;
                mbar_wait(mb_empty0 + 8u * slot, pu);
            }
            const int ks = s * BKH;
            const int w  = ks >> 8;
            const int d0 = ks & 255;
            const unsigned abase = smem_base + SM_DATA + slot * STAGE_B;
            const unsigned bbase = abase + A_TILE;
            // A: 1024 chunks / 32 lanes = 32 per lane
#pragma unroll
            for (int i = 0; i < 32; i++) {
                int c   = lane + i * 32;
                int row = c >> 3;
                int ch  = c & 7;
                int t   = t0 + row + w;
                cp16(abase + row * 128 + ((ch ^ (row & 7)) * 16),
                     midb + (long)t * DDIM + d0 + ch * 8, (t < NTOK) ? 16 : 0);
            }
            // B: 1024 chunks / 32 lanes
#pragma unroll
            for (int i = 0; i < 32; i++) {
                int c   = lane + i * 32;
                int row = c >> 3;
                int ch  = c & 7;
                cp16(bbase + row * 128 + ((ch ^ (row & 7)) * 16),
                     g_cwT + (long)(n0 + row) * KTOT + ks + ch * 8, 16);
            }
            asm volatile("cp.async.mbarrier.arrive.noinc.shared.b64 [%0];"
                         :: "r"(mb_full0 + 8u * slot) : "memory");
        }
        return;  // producer exits; no further CTA-wide syncs
    }

    // ----------------- CONSUMERS (warps 0-3) -----------------
    const int wm = warp >> 1;        // 0..1 -> m offset wm*64
    const int wn = warp & 1;         // 0..1 -> n offset wn*64
    const int gi = lane >> 2;
    const int tl = lane & 3;
    const int grp8 = lane >> 3;      // 0..3
    const int r8   = lane & 7;

    float acc[4][8][4];
#pragma unroll
    for (int mt = 0; mt < 4; mt++)
#pragma unroll
        for (int nt = 0; nt < 8; nt++)
#pragma unroll
            for (int i = 0; i < 4; i++) acc[mt][nt][i] = 0.f;

#pragma unroll 1
    for (int s = 0; s < NS; s++) {
        const int slot = s % NSLOT;
        mbar_wait(mb_full0 + 8u * slot, (s / NSLOT) & 1);

        const unsigned abase = smem_base + SM_DATA + slot * STAGE_B;
        const unsigned bbase = abase + A_TILE;

#pragma unroll
        for (int k4 = 0; k4 < 4; k4++) {          // 4 k16 slices per stage
            const int kc = k4 * 2;
            unsigned af[4][4];
            unsigned bf[4][4];
#pragma unroll
            for (int mt = 0; mt < 4; mt++) {
                int row = wm * 64 + mt * 16 + (grp8 & 1) * 8 + r8;
                int ch  = kc + (grp8 >> 1);
                ldsm4(af[mt], abase + row * 128 + ((ch ^ (row & 7)) * 16));
            }
#pragma unroll
            for (int q = 0; q < 4; q++) {
                int row = wn * 64 + q * 16 + (grp8 >> 1) * 8 + r8;
                int ch  = kc + (grp8 & 1);
                ldsm4(bf[q], bbase + row * 128 + ((ch ^ (row & 7)) * 16));
            }
#pragma unroll
            for (int mt = 0; mt < 4; mt++)
#pragma unroll
                for (int nt = 0; nt < 8; nt++)
                    mma_f16(acc[mt][nt], af[mt], &bf[nt >> 1][(nt & 1) * 2]);
        }

        // release slot: all lanes are past the warp-collective MMAs that
        // consumed this slot's smem, so one elected arrive per warp suffices
        if (lane == 0)
            asm volatile("mbarrier.arrive.shared.b64 _, [%0];"
                         :: "r"(mb_empty0 + 8u * slot) : "memory");
    }

    // epilogue: bias + leaky relu
#pragma unroll
    for (int mt = 0; mt < 4; mt++) {
        int r0 = t0 + wm * 64 + mt * 16 + gi;
        int r1 = r0 + 8;
#pragma unroll
        for (int nt = 0; nt < 8; nt++) {
            int c = n0 + wn * 64 + nt * 8 + 2 * tl;
            float2 bv = *(const float2*)(cb + c);
            if (r0 < TOUT) {
                float v0 = acc[mt][nt][0] + bv.x;
                float v1 = acc[mt][nt][1] + bv.y;
                v0 = (v0 >= 0.f) ? v0 : NEG_SLOPE * v0;
                v1 = (v1 >= 0.f) ? v1 : NEG_SLOPE * v1;
                *(float2*)(y + ((long)b * TOUT + r0) * OCH + c) = make_float2(v0, v1);
            }
            if (r1 < TOUT) {
                float v2 = acc[mt][nt][2] + bv.x;
                float v3 = acc[mt][nt][3] + bv.y;
                v2 = (v2 >= 0.f) ? v2 : NEG_SLOPE * v2;
                v3 = (v3 >= 0.f) ? v3 : NEG_SLOPE * v3;
                *(float2*)(y + ((long)b * TOUT + r1) * OCH + c) = make_float2(v2, v3);
            }
        }
    }
}

// ===========================================================================
extern "C" void kernel_launch(void* const* d_in, const int* in_sizes, int n_in,
                              void* d_out, int out_size) {
    const float* x    = (const float*)d_in[0];
    const int*   idx  = (const int*)  d_in[1];
    const float* W    = (const float*)d_in[2];
    const float* bias = (const float*)d_in[3];
    const float* cw   = (const float*)d_in[4];
    const float* cb   = (const float*)d_in[5];
    float* y = (float*)d_out;

    cudaFuncSetAttribute(conv_mma_kernel,
                         cudaFuncAttributeMaxDynamicSharedMemorySize, SM_TOTAL_CONV);

    trans_cw_kernel<<<dim3(OCH / 32, KTOT / 32), 256>>>(cw);

    dim3 grid1(DDIM / 128, (BATCH * SEQ) / 128, GRP);   // (2, 16, 16)
    gemm1_mma_kernel<<<grid1, 256>>>(x, idx, W, bias);

    dim3 grid2(OCH / 128, NTOK / 128, BATCH);           // (4, 8, 32) = 1024 CTAs
    conv_mma_kernel<<<grid2, 160, SM_TOTAL_CONV>>>(cb, y);
}

// round 12
// speedup vs baseline: 3.2241x; 1.0561x over previous
#include <cuda_runtime.h>
#include <cuda_fp16.h>
#include <cstdint>

// Problem constants
#define BATCH 32
#define NTOK  1024
#define FDIM  512
#define GRP   16
#define SEQ   64
#define DDIM  256
#define WIN   32
#define OCH   512
#define TOUT  993          // NTOK - WIN + 1
#define KTOT  (WIN * DDIM) // 8192
#define NEG_SLOPE 0.2f

// Scratch (device globals; no allocs allowed)
__device__ __half g_mid[BATCH * NTOK * DDIM];         // 16 MB, fp16 mid
__device__ __half g_cwT[OCH * KTOT];                  // 8 MB, conv_w transposed [O][K], fp16
__device__ __half g_xh [BATCH * NTOK * FDIM];         // 32 MB, x in fp16
__device__ __half g_wT [GRP * DDIM * FDIM];           // 4 MB, W transposed [g][d][f], fp16

__device__ __forceinline__ void cp16(unsigned smem, const void* g, int sz) {
    asm volatile("cp.async.ca.shared.global [%0], [%1], 16, %2;\n"
                 :: "r"(smem), "l"(g), "r"(sz));
}

__device__ __forceinline__ void ldsm4(unsigned* r, unsigned addr) {
    asm volatile("ldmatrix.sync.aligned.m8n8.x4.shared.b16 {%0,%1,%2,%3}, [%4];"
                 : "=r"(r[0]), "=r"(r[1]), "=r"(r[2]), "=r"(r[3]) : "r"(addr));
}

__device__ __forceinline__ void mma_f16(float* c, const unsigned* a, const unsigned* b) {
    asm volatile(
        "mma.sync.aligned.m16n8k16.row.col.f32.f16.f16.f32 "
        "{%0,%1,%2,%3}, {%4,%5,%6,%7}, {%8,%9}, {%0,%1,%2,%3};\n"
        : "+f"(c[0]), "+f"(c[1]), "+f"(c[2]), "+f"(c[3])
        : "r"(a[0]), "r"(a[1]), "r"(a[2]), "r"(a[3]), "r"(b[0]), "r"(b[1]));
}

// ===========================================================================
// Pre-pass kernels
// ===========================================================================
// x fp32 -> fp16 (element count 16.7M, vectorized)
__global__ __launch_bounds__(256)
void cvt_x_kernel(const float* __restrict__ x) {
    long i = ((long)blockIdx.x * 256 + threadIdx.x) * 8;
    float4 v0 = *(const float4*)(x + i);
    float4 v1 = *(const float4*)(x + i + 4);
    __half2* o = (__half2*)(g_xh + i);
    o[0] = __floats2half2_rn(v0.x, v0.y);
    o[1] = __floats2half2_rn(v0.z, v0.w);
    o[2] = __floats2half2_rn(v1.x, v1.y);
    o[3] = __floats2half2_rn(v1.z, v1.w);
}

// transpose W [g][f=512][d=256] -> g_wT [g][d=256][f=512], fp16
__global__ __launch_bounds__(256)
void trans_w_kernel(const float* __restrict__ W) {
    __shared__ float tile[32][33];
    const int g  = blockIdx.z;
    const int d0 = blockIdx.x * 32;
    const int f0 = blockIdx.y * 32;
    const int tx = threadIdx.x & 31;
    const int ty = threadIdx.x >> 5;
    const float* Wg = W + (long)g * FDIM * DDIM;
#pragma unroll
    for (int j = 0; j < 4; j++) {
        int f = ty + j * 8;
        tile[f][tx] = Wg[(long)(f0 + f) * DDIM + d0 + tx];
    }
    __syncthreads();
    __half* dst = g_wT + (long)g * DDIM * FDIM;
#pragma unroll
    for (int j = 0; j < 4; j++) {
        int d = ty + j * 8;
        dst[(long)(d0 + d) * FDIM + f0 + tx] = __float2half_rn(tile[tx][d]);
    }
}

// transpose conv_w [K=8192][O=512] -> g_cwT [O=512][K=8192], fp16
__global__ __launch_bounds__(256)
void trans_cw_kernel(const float* __restrict__ cw) {
    __shared__ float tile[32][33];
    const int o0 = blockIdx.x * 32;
    const int k0 = blockIdx.y * 32;
    const int tx = threadIdx.x & 31;
    const int ty = threadIdx.x >> 5;
#pragma unroll
    for (int j = 0; j < 4; j++) {
        int k = ty + j * 8;
        tile[k][tx] = cw[(long)(k0 + k) * OCH + o0 + tx];
    }
    __syncthreads();
#pragma unroll
    for (int j = 0; j < 4; j++) {
        int o = ty + j * 8;
        g_cwT[(long)(o0 + o) * KTOT + k0 + tx] = __float2half_rn(tile[tx][o]);
    }
}

// ===========================================================================
// Kernel 1: gather + grouped GEMM, fp16 m16n8k16 (clone of conv structure).
//   Per group g: M=2048 (b*64+s, gathered x rows), N=256 (d), K=512 (f).
//   CTA 128x128, 4 warps (2m x 2n), warp 64x64, BKH=64, 8 stages, 3-slot ring.
//   Epilogue: +bias, fp16, scatter to g_mid[b, g*64+s, d].
// ===========================================================================
#define BKH 64
#define A_TILE 16384                 // 128 rows * 64 halves * 2B
#define STAGE_B 32768
#define G1_SMEM (3 * STAGE_B + 512)  // + rowbase

__global__ __launch_bounds__(128, 2)
void gemm1_mma_kernel(const int* __restrict__ idx, const float* __restrict__ bias) {
    extern __shared__ __align__(128) char smem[];
    unsigned smem_base;
    asm("{ .reg .u64 t; cvta.to.shared.u64 t, %1; cvt.u32.u64 %0, t; }"
        : "=r"(smem_base) : "l"(smem));
    int* rowbase = (int*)(smem + 3 * STAGE_B);   // 128 ints

    const int grp = blockIdx.z;
    const int m0  = blockIdx.y * 128;
    const int n0  = blockIdx.x * 128;
    const int tid  = threadIdx.x;
    const int lane = tid & 31;
    const int warp = tid >> 5;
    const int wm = warp >> 1;
    const int wn = warp & 1;
    const int gi = lane >> 2;
    const int tl = lane & 3;
    const int grp8 = lane >> 3;
    const int r8   = lane & 7;

    if (tid < 128) {
        int m  = m0 + tid;
        int bb = m >> 6;
        int s  = m & 63;
        rowbase[tid] = bb * NTOK + idx[grp * SEQ + s];
    }
    __syncthreads();

    const __half* Bsrc = g_wT + (long)grp * DDIM * FDIM;

    float acc[4][8][4];
#pragma unroll
    for (int mt = 0; mt < 4; mt++)
#pragma unroll
        for (int nt = 0; nt < 8; nt++)
#pragma unroll
            for (int i = 0; i < 4; i++) acc[mt][nt][i] = 0.f;

    const int NS = FDIM / BKH;   // 8

    auto load_stage = [&](int it) {
        const int ks = it * BKH;
        const int buf = it % 3;
        const unsigned abase = smem_base + buf * STAGE_B;
        const unsigned bbase = abase + A_TILE;
#pragma unroll
        for (int i = 0; i < 8; i++) {
            int c   = tid + i * 128;
            int row = c >> 3;
            int ch  = c & 7;
            cp16(abase + row * 128 + ((ch ^ (row & 7)) * 16),
                 g_xh + (long)rowbase[row] * FDIM + ks + ch * 8, 16);
        }
#pragma unroll
        for (int i = 0; i < 8; i++) {
            int c   = tid + i * 128;
            int row = c >> 3;
            int ch  = c & 7;
            cp16(bbase + row * 128 + ((ch ^ (row & 7)) * 16),
                 Bsrc + (long)(n0 + row) * FDIM + ks + ch * 8, 16);
        }
        asm volatile("cp.async.commit_group;\n");
    };

    load_stage(0);
    load_stage(1);

#pragma unroll 1
    for (int s = 0; s < NS; s++) {
        if (s + 1 < NS) asm volatile("cp.async.wait_group 1;\n");
        else            asm volatile("cp.async.wait_group 0;\n");
        __syncthreads();

        if (s + 2 < NS) load_stage(s + 2);

        const int buf = s % 3;
        const unsigned abase = smem_base + buf * STAGE_B;
        const unsigned bbase = abase + A_TILE;

#pragma unroll
        for (int k4 = 0; k4 < 4; k4++) {
            const int kc = k4 * 2;
            unsigned af[4][4];
            unsigned bf[4][4];
#pragma unroll
            for (int mt = 0; mt < 4; mt++) {
                int row = wm * 64 + mt * 16 + (grp8 & 1) * 8 + r8;
                int ch  = kc + (grp8 >> 1);
                ldsm4(af[mt], abase + row * 128 + ((ch ^ (row & 7)) * 16));
            }
#pragma unroll
            for (int q = 0; q < 4; q++) {
                int row = wn * 64 + q * 16 + (grp8 >> 1) * 8 + r8;
                int ch  = kc + (grp8 & 1);
                ldsm4(bf[q], bbase + row * 128 + ((ch ^ (row & 7)) * 16));
            }
#pragma unroll
            for (int mt = 0; mt < 4; mt++)
#pragma unroll
                for (int nt = 0; nt < 8; nt++)
                    mma_f16(acc[mt][nt], af[mt], &bf[nt >> 1][(nt & 1) * 2]);
        }
    }

    // epilogue: + bias, fp16, scatter rows m -> (b, grp*64+s)
#pragma unroll
    for (int mt = 0; mt < 4; mt++) {
        int r0 = m0 + wm * 64 + mt * 16 + gi;
        int r1 = r0 + 8;
#pragma unroll
        for (int nt = 0; nt < 8; nt++) {
            int c = n0 + wn * 64 + nt * 8 + 2 * tl;
            float2 bv = *(const float2*)(bias + grp * DDIM + c);
            {
                int bb = r0 >> 6, s = r0 & 63;
                __half2* dst = (__half2*)(g_mid + ((long)(bb * NTOK + grp * SEQ + s)) * DDIM + c);
                *dst = __floats2half2_rn(acc[mt][nt][0] + bv.x, acc[mt][nt][1] + bv.y);
            }
            {
                int bb = r1 >> 6, s = r1 & 63;
                __half2* dst = (__half2*)(g_mid + ((long)(bb * NTOK + grp * SEQ + s)) * DDIM + c);
                *dst = __floats2half2_rn(acc[mt][nt][2] + bv.x, acc[mt][nt][3] + bv.y);
            }
        }
    }
}

// ===========================================================================
// Kernel 2: conv1d implicit GEMM, fp16 m16n8k16 — R7 kernel, UNCHANGED.
//   CTA 128x128, 4 warps (2m x 2n), warp 64x64, BKH=64, 3-stage cp.async.
//   Rows 128B; 16B chunks XOR-swizzled; fragment double-buffering.
// ===========================================================================
#define SM_TOTAL_CONV (6 * A_TILE)   // 96 KB

__global__ __launch_bounds__(128, 2)
void conv_mma_kernel(const float* __restrict__ cb, float* __restrict__ y) {
    extern __shared__ __align__(128) char smem[];
    unsigned smem_base;
    asm("{ .reg .u64 t; cvta.to.shared.u64 t, %1; cvt.u32.u64 %0, t; }"
        : "=r"(smem_base) : "l"(smem));

    const int b  = blockIdx.z;
    const int t0 = blockIdx.y * 128;
    const int n0 = blockIdx.x * 128;
    const int tid  = threadIdx.x;
    const int lane = tid & 31;
    const int warp = tid >> 5;
    const int wm = warp >> 1;
    const int wn = warp & 1;
    const int gi = lane >> 2;
    const int tl = lane & 3;
    const int grp8 = lane >> 3;
    const int r8   = lane & 7;

    const __half* midb = g_mid + (long)b * NTOK * DDIM;

    float acc[4][8][4];
#pragma unroll
    for (int mt = 0; mt < 4; mt++)
#pragma unroll
        for (int nt = 0; nt < 8; nt++)
#pragma unroll
            for (int i = 0; i < 4; i++) acc[mt][nt][i] = 0.f;

    const int NS = KTOT / BKH;   // 128

    auto load_stage = [&](int it) {
        const int ks = it * BKH;
        const int w  = ks >> 8;
        const int d0 = ks & 255;
        const int buf = it % 3;
        const unsigned abase = smem_base + buf * STAGE_B;
        const unsigned bbase = abase + A_TILE;
#pragma unroll
        for (int i = 0; i < 8; i++) {
            int c   = tid + i * 128;
            int row = c >> 3;
            int ch  = c & 7;
            int t   = t0 + row + w;
            cp16(abase + row * 128 + ((ch ^ (row & 7)) * 16),
                 midb + (long)t * DDIM + d0 + ch * 8, (t < NTOK) ? 16 : 0);
        }
#pragma unroll
        for (int i = 0; i < 8; i++) {
            int c   = tid + i * 128;
            int row = c >> 3;
            int ch  = c & 7;
            cp16(bbase + row * 128 + ((ch ^ (row & 7)) * 16),
                 g_cwT + (long)(n0 + row) * KTOT + ks + ch * 8, 16);
        }
        asm volatile("cp.async.commit_group;\n");
    };

    auto ldfrag = [&](unsigned af[4][4], unsigned bf[4][4],
                      int kc, unsigned abase, unsigned bbase) {
#pragma unroll
        for (int mt = 0; mt < 4; mt++) {
            int row = wm * 64 + mt * 16 + (grp8 & 1) * 8 + r8;
            int ch  = kc + (grp8 >> 1);
            ldsm4(af[mt], abase + row * 128 + ((ch ^ (row & 7)) * 16));
        }
#pragma unroll
        for (int q = 0; q < 4; q++) {
            int row = wn * 64 + q * 16 + (grp8 >> 1) * 8 + r8;
            int ch  = kc + (grp8 & 1);
            ldsm4(bf[q], bbase + row * 128 + ((ch ^ (row & 7)) * 16));
        }
    };

    load_stage(0);
    load_stage(1);

    unsigned af[2][4][4];
    unsigned bf[2][4][4];

#pragma unroll 1
    for (int s = 0; s < NS; s++) {
        if (s + 1 < NS) asm volatile("cp.async.wait_group 1;\n");
        else            asm volatile("cp.async.wait_group 0;\n");
        __syncthreads();

        if (s + 2 < NS) load_stage(s + 2);

        const int buf = s % 3;
        const unsigned abase = smem_base + buf * STAGE_B;
        const unsigned bbase = abase + A_TILE;

        ldfrag(af[0], bf[0], 0, abase, bbase);

#pragma unroll
        for (int k4 = 0; k4 < 4; k4++) {
            const int cur = k4 & 1;
            if (k4 < 3)
                ldfrag(af[cur ^ 1], bf[cur ^ 1], (k4 + 1) * 2, abase, bbase);
#pragma unroll
            for (int mt = 0; mt < 4; mt++)
#pragma unroll
                for (int nt = 0; nt < 8; nt++)
                    mma_f16(acc[mt][nt], af[cur][mt], &bf[cur][nt >> 1][(nt & 1) * 2]);
        }
    }

    // epilogue: bias + leaky relu
#pragma unroll
    for (int mt = 0; mt < 4; mt++) {
        int r0 = t0 + wm * 64 + mt * 16 + gi;
        int r1 = r0 + 8;
#pragma unroll
        for (int nt = 0; nt < 8; nt++) {
            int c = n0 + wn * 64 + nt * 8 + 2 * tl;
            float2 bv = *(const float2*)(cb + c);
            if (r0 < TOUT) {
                float v0 = acc[mt][nt][0] + bv.x;
                float v1 = acc[mt][nt][1] + bv.y;
                v0 = (v0 >= 0.f) ? v0 : NEG_SLOPE * v0;
                v1 = (v1 >= 0.f) ? v1 : NEG_SLOPE * v1;
                *(float2*)(y + ((long)b * TOUT + r0) * OCH + c) = make_float2(v0, v1);
            }
            if (r1 < TOUT) {
                float v2 = acc[mt][nt][2] + bv.x;
                float v3 = acc[mt][nt][3] + bv.y;
                v2 = (v2 >= 0.f) ? v2 : NEG_SLOPE * v2;
                v3 = (v3 >= 0.f) ? v3 : NEG_SLOPE * v3;
                *(float2*)(y + ((long)b * TOUT + r1) * OCH + c) = make_float2(v2, v3);
            }
        }
    }
}

// ===========================================================================
extern "C" void kernel_launch(void* const* d_in, const int* in_sizes, int n_in,
                              void* d_out, int out_size) {
    const float* x    = (const float*)d_in[0];
    const int*   idx  = (const int*)  d_in[1];
    const float* W    = (const float*)d_in[2];
    const float* bias = (const float*)d_in[3];
    const float* cw   = (const float*)d_in[4];
    const float* cb   = (const float*)d_in[5];
    float* y = (float*)d_out;

    cudaFuncSetAttribute(conv_mma_kernel,
                         cudaFuncAttributeMaxDynamicSharedMemorySize, SM_TOTAL_CONV);
    cudaFuncSetAttribute(gemm1_mma_kernel,
                         cudaFuncAttributeMaxDynamicSharedMemorySize, G1_SMEM);

    cvt_x_kernel<<<(BATCH * NTOK * FDIM) / (256 * 8), 256>>>(x);
    trans_w_kernel<<<dim3(DDIM / 32, FDIM / 32, GRP), 256>>>(W);
    trans_cw_kernel<<<dim3(OCH / 32, KTOT / 32), 256>>>(cw);

    dim3 grid1(DDIM / 128, (BATCH * SEQ) / 128, GRP);   // (2, 16, 16)
    gemm1_mma_kernel<<<grid1, 128, G1_SMEM>>>(idx, bias);

    dim3 grid2(OCH / 128, NTOK / 128, BATCH);           // (4, 8, 32)
    conv_mma_kernel<<<grid2, 128, SM_TOTAL_CONV>>>(cb, y);
}

// round 13
// speedup vs baseline: 3.2413x; 1.0053x over previous
#include <cuda_runtime.h>
#include <cuda_fp16.h>
#include <cstdint>

// Problem constants
#define BATCH 32
#define NTOK  1024
#define FDIM  512
#define GRP   16
#define SEQ   64
#define DDIM  256
#define WIN   32
#define OCH   512
#define TOUT  993          // NTOK - WIN + 1
#define KTOT  (WIN * DDIM) // 8192
#define NEG_SLOPE 0.2f

// Scratch (device globals; no allocs allowed)
__device__ __half g_mid[BATCH * NTOK * DDIM];         // 16 MB, fp16 mid
__device__ __half g_cwT[OCH * KTOT];                  // 8 MB, conv_w transposed [O][K], fp16
__device__ __half g_xh [BATCH * NTOK * FDIM];         // 32 MB, x in fp16
__device__ __half g_wT [GRP * DDIM * FDIM];           // 4 MB, W transposed [g][d][f], fp16

__device__ __forceinline__ void cp16(unsigned smem, const void* g, int sz) {
    asm volatile("cp.async.ca.shared.global [%0], [%1], 16, %2;\n"
                 :: "r"(smem), "l"(g), "r"(sz));
}

__device__ __forceinline__ void ldsm4(unsigned* r, unsigned addr) {
    asm volatile("ldmatrix.sync.aligned.m8n8.x4.shared.b16 {%0,%1,%2,%3}, [%4];"
                 : "=r"(r[0]), "=r"(r[1]), "=r"(r[2]), "=r"(r[3]) : "r"(addr));
}

__device__ __forceinline__ void mma_f16(float* c, const unsigned* a, const unsigned* b) {
    asm volatile(
        "mma.sync.aligned.m16n8k16.row.col.f32.f16.f16.f32 "
        "{%0,%1,%2,%3}, {%4,%5,%6,%7}, {%8,%9}, {%0,%1,%2,%3};\n"
        : "+f"(c[0]), "+f"(c[1]), "+f"(c[2]), "+f"(c[3])
        : "r"(a[0]), "r"(a[1]), "r"(a[2]), "r"(a[3]), "r"(b[0]), "r"(b[1]));
}

// ===========================================================================
// Fused pre-pass: one launch does cvt_x | trans_w | trans_cw, partitioned by
// blockIdx.x. All three are independent and memory-bound.
//   [0, 8192)          cvt_x   : x fp32 -> g_xh fp16 (8 elems/thread)
//   [8192, 10240)      trans_w : W [g][f][d] -> g_wT [g][d][f] fp16
//   [10240, 14336)     trans_cw: cw [K][O] -> g_cwT [O][K] fp16
// ===========================================================================
#define PREP_CVTX   8192
#define PREP_TRW    (PREP_CVTX + 2048)
#define PREP_TOTAL  (PREP_TRW + 4096)

__global__ __launch_bounds__(256)
void prep_kernel(const float* __restrict__ x, const float* __restrict__ W,
                 const float* __restrict__ cw) {
    __shared__ float tile[32][33];
    const int bx = blockIdx.x;
    const int tx = threadIdx.x & 31;
    const int ty = threadIdx.x >> 5;

    if (bx < PREP_CVTX) {
        long i = ((long)bx * 256 + threadIdx.x) * 8;
        float4 v0 = *(const float4*)(x + i);
        float4 v1 = *(const float4*)(x + i + 4);
        __half2* o = (__half2*)(g_xh + i);
        o[0] = __floats2half2_rn(v0.x, v0.y);
        o[1] = __floats2half2_rn(v0.z, v0.w);
        o[2] = __floats2half2_rn(v1.x, v1.y);
        o[3] = __floats2half2_rn(v1.z, v1.w);
    } else if (bx < PREP_TRW) {
        // trans_w: 128 blocks per group (8 d-blocks x 16 f-blocks)
        int t  = bx - PREP_CVTX;
        int g  = t >> 7;
        int rem = t & 127;
        int d0 = (rem >> 4) * 32;
        int f0 = (rem & 15) * 32;
        const float* Wg = W + (long)g * FDIM * DDIM;
#pragma unroll
        for (int j = 0; j < 4; j++) {
            int f = ty + j * 8;
            tile[f][tx] = Wg[(long)(f0 + f) * DDIM + d0 + tx];
        }
        __syncthreads();
        __half* dst = g_wT + (long)g * DDIM * FDIM;
#pragma unroll
        for (int j = 0; j < 4; j++) {
            int d = ty + j * 8;
            dst[(long)(d0 + d) * FDIM + f0 + tx] = __float2half_rn(tile[tx][d]);
        }
    } else {
        // trans_cw: 16 o-blocks x 256 k-blocks
        int t  = bx - PREP_TRW;
        int o0 = (t >> 8) * 32;
        int k0 = (t & 255) * 32;
#pragma unroll
        for (int j = 0; j < 4; j++) {
            int k = ty + j * 8;
            tile[k][tx] = cw[(long)(k0 + k) * OCH + o0 + tx];
        }
        __syncthreads();
#pragma unroll
        for (int j = 0; j < 4; j++) {
            int o = ty + j * 8;
            g_cwT[(long)(o0 + o) * KTOT + k0 + tx] = __float2half_rn(tile[tx][o]);
        }
    }
}

// ===========================================================================
// Kernel 1: gather + grouped GEMM, fp16 m16n8k16.
//   Per group g: M=2048, N=256, K=512. Each CTA covers TWO 128x128 m-tiles
//   sequentially (16 pipeline stages; mid-loop epilogue at s==8) so the grid
//   is 256 CTAs = one full wave with no tail, and the pipeline prologue is
//   amortized once. CTA 128x128 per m-tile, 4 warps (2m x 2n), warp 64x64.
// ===========================================================================
#define BKH 64
#define A_TILE 16384                 // 128 rows * 64 halves * 2B
#define STAGE_B 32768
#define G1_SMEM (3 * STAGE_B + 1024) // + rowbase[256]

__global__ __launch_bounds__(128, 2)
void gemm1_mma_kernel(const int* __restrict__ idx, const float* __restrict__ bias) {
    extern __shared__ __align__(128) char smem[];
    unsigned smem_base;
    asm("{ .reg .u64 t; cvta.to.shared.u64 t, %1; cvt.u32.u64 %0, t; }"
        : "=r"(smem_base) : "l"(smem));
    int* rowbase = (int*)(smem + 3 * STAGE_B);   // 256 ints

    const int grp   = blockIdx.z;
    const int mpair = blockIdx.y;            // 0..7 -> rows [mpair*256, +256)
    const int n0    = blockIdx.x * 128;
    const int tid  = threadIdx.x;
    const int lane = tid & 31;
    const int warp = tid >> 5;
    const int wm = warp >> 1;
    const int wn = warp & 1;
    const int gi = lane >> 2;
    const int tl = lane & 3;
    const int grp8 = lane >> 3;
    const int r8   = lane & 7;

    // 256 gathered row bases
#pragma unroll
    for (int j = 0; j < 2; j++) {
        int m  = mpair * 256 + tid + j * 128;
        int bb = m >> 6;
        int s  = m & 63;
        rowbase[tid + j * 128] = bb * NTOK + idx[grp * SEQ + s];
    }
    __syncthreads();

    const __half* Bsrc = g_wT + (long)grp * DDIM * FDIM;

    float acc[4][8][4];
#pragma unroll
    for (int mt = 0; mt < 4; mt++)
#pragma unroll
        for (int nt = 0; nt < 8; nt++)
#pragma unroll
            for (int i = 0; i < 4; i++) acc[mt][nt][i] = 0.f;

    const int NS = 16;   // 2 m-tiles x 8 k-stages

    auto load_stage = [&](int it) {
        const int mt2 = it >> 3;             // which m-tile
        const int ks  = (it & 7) * BKH;
        const int buf = it % 3;
        const unsigned abase = smem_base + buf * STAGE_B;
        const unsigned bbase = abase + A_TILE;
#pragma unroll
        for (int i = 0; i < 8; i++) {
            int c   = tid + i * 128;
            int row = c >> 3;
            int ch  = c & 7;
            cp16(abase + row * 128 + ((ch ^ (row & 7)) * 16),
                 g_xh + (long)rowbase[mt2 * 128 + row] * FDIM + ks + ch * 8, 16);
        }
#pragma unroll
        for (int i = 0; i < 8; i++) {
            int c   = tid + i * 128;
            int row = c >> 3;
            int ch  = c & 7;
            cp16(bbase + row * 128 + ((ch ^ (row & 7)) * 16),
                 Bsrc + (long)(n0 + row) * FDIM + ks + ch * 8, 16);
        }
        asm volatile("cp.async.commit_group;\n");
    };

    // epilogue for one m-tile: + bias, fp16, scatter to g_mid
    auto epilogue = [&](int mt2) {
        const int mbase = mpair * 256 + mt2 * 128;
#pragma unroll
        for (int mt = 0; mt < 4; mt++) {
            int r0 = mbase + wm * 64 + mt * 16 + gi;
            int r1 = r0 + 8;
#pragma unroll
            for (int nt = 0; nt < 8; nt++) {
                int c = n0 + wn * 64 + nt * 8 + 2 * tl;
                float2 bv = *(const float2*)(bias + grp * DDIM + c);
                {
                    int bb = r0 >> 6, s = r0 & 63;
                    __half2* dst = (__half2*)(g_mid + ((long)(bb * NTOK + grp * SEQ + s)) * DDIM + c);
                    *dst = __floats2half2_rn(acc[mt][nt][0] + bv.x, acc[mt][nt][1] + bv.y);
                }
                {
                    int bb = r1 >> 6, s = r1 & 63;
                    __half2* dst = (__half2*)(g_mid + ((long)(bb * NTOK + grp * SEQ + s)) * DDIM + c);
                    *dst = __floats2half2_rn(acc[mt][nt][2] + bv.x, acc[mt][nt][3] + bv.y);
                }
                acc[mt][nt][0] = 0.f; acc[mt][nt][1] = 0.f;
                acc[mt][nt][2] = 0.f; acc[mt][nt][3] = 0.f;
            }
        }
    };

    load_stage(0);
    load_stage(1);

#pragma unroll 1
    for (int s = 0; s < NS; s++) {
        if (s + 1 < NS) asm volatile("cp.async.wait_group 1;\n");
        else            asm volatile("cp.async.wait_group 0;\n");
        __syncthreads();

        if (s == 8) epilogue(0);     // m-tile 0 done after stage 7's compute

        if (s + 2 < NS) load_stage(s + 2);

        const int buf = s % 3;
        const unsigned abase = smem_base + buf * STAGE_B;
        const unsigned bbase = abase + A_TILE;

#pragma unroll
        for (int k4 = 0; k4 < 4; k4++) {
            const int kc = k4 * 2;
            unsigned af[4][4];
            unsigned bf[4][4];
#pragma unroll
            for (int mt = 0; mt < 4; mt++) {
                int row = wm * 64 + mt * 16 + (grp8 & 1) * 8 + r8;
                int ch  = kc + (grp8 >> 1);
                ldsm4(af[mt], abase + row * 128 + ((ch ^ (row & 7)) * 16));
            }
#pragma unroll
            for (int q = 0; q < 4; q++) {
                int row = wn * 64 + q * 16 + (grp8 >> 1) * 8 + r8;
                int ch  = kc + (grp8 & 1);
                ldsm4(bf[q], bbase + row * 128 + ((ch ^ (row & 7)) * 16));
            }
#pragma unroll
            for (int mt = 0; mt < 4; mt++)
#pragma unroll
                for (int nt = 0; nt < 8; nt++)
                    mma_f16(acc[mt][nt], af[mt], &bf[nt >> 1][(nt & 1) * 2]);
        }
    }

    epilogue(1);
}

// ===========================================================================
// Kernel 2: conv1d implicit GEMM, fp16 m16n8k16 — R7 kernel, UNCHANGED.
//   CTA 128x128, 4 warps (2m x 2n), warp 64x64, BKH=64, 3-stage cp.async.
//   Rows 128B; 16B chunks XOR-swizzled; fragment double-buffering.
// ===========================================================================
#define SM_TOTAL_CONV (6 * A_TILE)   // 96 KB

__global__ __launch_bounds__(128, 2)
void conv_mma_kernel(const float* __restrict__ cb, float* __restrict__ y) {
    extern __shared__ __align__(128) char smem[];
    unsigned smem_base;
    asm("{ .reg .u64 t; cvta.to.shared.u64 t, %1; cvt.u32.u64 %0, t; }"
        : "=r"(smem_base) : "l"(smem));

    const int b  = blockIdx.z;
    const int t0 = blockIdx.y * 128;
    const int n0 = blockIdx.x * 128;
    const int tid  = threadIdx.x;
    const int lane = tid & 31;
    const int warp = tid >> 5;
    const int wm = warp >> 1;
    const int wn = warp & 1;
    const int gi = lane >> 2;
    const int tl = lane & 3;
    const int grp8 = lane >> 3;
    const int r8   = lane & 7;

    const __half* midb = g_mid + (long)b * NTOK * DDIM;

    float acc[4][8][4];
#pragma unroll
    for (int mt = 0; mt < 4; mt++)
#pragma unroll
        for (int nt = 0; nt < 8; nt++)
#pragma unroll
            for (int i = 0; i < 4; i++) acc[mt][nt][i] = 0.f;

    const int NS = KTOT / BKH;   // 128

    auto load_stage = [&](int it) {
        const int ks = it * BKH;
        const int w  = ks >> 8;
        const int d0 = ks & 255;
        const int buf = it % 3;
        const unsigned abase = smem_base + buf * STAGE_B;
        const unsigned bbase = abase + A_TILE;
#pragma unroll
        for (int i = 0; i < 8; i++) {
            int c   = tid + i * 128;
            int row = c >> 3;
            int ch  = c & 7;
            int t   = t0 + row + w;
            cp16(abase + row * 128 + ((ch ^ (row & 7)) * 16),
                 midb + (long)t * DDIM + d0 + ch * 8, (t < NTOK) ? 16 : 0);
        }
#pragma unroll
        for (int i = 0; i < 8; i++) {
            int c   = tid + i * 128;
            int row = c >> 3;
            int ch  = c & 7;
            cp16(bbase + row * 128 + ((ch ^ (row & 7)) * 16),
                 g_cwT + (long)(n0 + row) * KTOT + ks + ch * 8, 16);
        }
        asm volatile("cp.async.commit_group;\n");
    };

    auto ldfrag = [&](unsigned af[4][4], unsigned bf[4][4],
                      int kc, unsigned abase, unsigned bbase) {
#pragma unroll
        for (int mt = 0; mt < 4; mt++) {
            int row = wm * 64 + mt * 16 + (grp8 & 1) * 8 + r8;
            int ch  = kc + (grp8 >> 1);
            ldsm4(af[mt], abase + row * 128 + ((ch ^ (row & 7)) * 16));
        }
#pragma unroll
        for (int q = 0; q < 4; q++) {
            int row = wn * 64 + q * 16 + (grp8 >> 1) * 8 + r8;
            int ch  = kc + (grp8 & 1);
            ldsm4(bf[q], bbase + row * 128 + ((ch ^ (row & 7)) * 16));
        }
    };

    load_stage(0);
    load_stage(1);

    unsigned af[2][4][4];
    unsigned bf[2][4][4];

#pragma unroll 1
    for (int s = 0; s < NS; s++) {
        if (s + 1 < NS) asm volatile("cp.async.wait_group 1;\n");
        else            asm volatile("cp.async.wait_group 0;\n");
        __syncthreads();

        if (s + 2 < NS) load_stage(s + 2);

        const int buf = s % 3;
        const unsigned abase = smem_base + buf * STAGE_B;
        const unsigned bbase = abase + A_TILE;

        ldfrag(af[0], bf[0], 0, abase, bbase);

#pragma unroll
        for (int k4 = 0; k4 < 4; k4++) {
            const int cur = k4 & 1;
            if (k4 < 3)
                ldfrag(af[cur ^ 1], bf[cur ^ 1], (k4 + 1) * 2, abase, bbase);
#pragma unroll
            for (int mt = 0; mt < 4; mt++)
#pragma unroll
                for (int nt = 0; nt < 8; nt++)
                    mma_f16(acc[mt][nt], af[cur][mt], &bf[cur][nt >> 1][(nt & 1) * 2]);
        }
    }

    // epilogue: bias + leaky relu
#pragma unroll
    for (int mt = 0; mt < 4; mt++) {
        int r0 = t0 + wm * 64 + mt * 16 + gi;
        int r1 = r0 + 8;
#pragma unroll
        for (int nt = 0; nt < 8; nt++) {
            int c = n0 + wn * 64 + nt * 8 + 2 * tl;
            float2 bv = *(const float2*)(cb + c);
            if (r0 < TOUT) {
                float v0 = acc[mt][nt][0] + bv.x;
                float v1 = acc[mt][nt][1] + bv.y;
                v0 = (v0 >= 0.f) ? v0 : NEG_SLOPE * v0;
                v1 = (v1 >= 0.f) ? v1 : NEG_SLOPE * v1;
                *(float2*)(y + ((long)b * TOUT + r0) * OCH + c) = make_float2(v0, v1);
            }
            if (r1 < TOUT) {
                float v2 = acc[mt][nt][2] + bv.x;
                float v3 = acc[mt][nt][3] + bv.y;
                v2 = (v2 >= 0.f) ? v2 : NEG_SLOPE * v2;
                v3 = (v3 >= 0.f) ? v3 : NEG_SLOPE * v3;
                *(float2*)(y + ((long)b * TOUT + r1) * OCH + c) = make_float2(v2, v3);
            }
        }
    }
}

// ===========================================================================
extern "C" void kernel_launch(void* const* d_in, const int* in_sizes, int n_in,
                              void* d_out, int out_size) {
    const float* x    = (const float*)d_in[0];
    const int*   idx  = (const int*)  d_in[1];
    const float* W    = (const float*)d_in[2];
    const float* bias = (const float*)d_in[3];
    const float* cw   = (const float*)d_in[4];
    const float* cb   = (const float*)d_in[5];
    float* y = (float*)d_out;

    cudaFuncSetAttribute(conv_mma_kernel,
                         cudaFuncAttributeMaxDynamicSharedMemorySize, SM_TOTAL_CONV);
    cudaFuncSetAttribute(gemm1_mma_kernel,
                         cudaFuncAttributeMaxDynamicSharedMemorySize, G1_SMEM);

    prep_kernel<<<PREP_TOTAL, 256>>>(x, W, cw);

    dim3 grid1(DDIM / 128, (BATCH * SEQ) / 256, GRP);   // (2, 8, 16) = 256 CTAs
    gemm1_mma_kernel<<<grid1, 128, G1_SMEM>>>(idx, bias);

    dim3 grid2(OCH / 128, NTOK / 128, BATCH);           // (4, 8, 32)
    conv_mma_kernel<<<grid2, 128, SM_TOTAL_CONV>>>(cb, y);
}